// round 2
// baseline (speedup 1.0000x reference)
#include <cuda_runtime.h>
#include <cuda_bf16.h>

// BilinearInterpolation (spatial transformer grid sample)
// X: [B, C, H, W] fp32, theta: [B, 6] fp32 -> out: [B, C, H_OUT, W_OUT] fp32
// Output element (b, c, iy, ix) samples at grid point:
//   xc = -1 + ix * 2/(W_OUT-1),  yc = -1 + iy * 2/(H_OUT-1)
//   xs = t00*xc + t01*yc + t02 ; ys = t10*xc + t11*yc + t12
//   x = (xs+1)*W/2 ; y = (ys+1)*H/2 ; bilinear with corners clipped to bounds,
//   weights computed from CLIPPED corner coords (matches reference exactly).

namespace {
constexpr int B = 16, C = 64, H = 256, W = 256;
constexpr int H_OUT = 256, W_OUT = 256;
constexpr int HW = H * W;           // channel stride in X
constexpr int HWO = H_OUT * W_OUT;  // channel stride in out
}

__global__ __launch_bounds__(256, 8)
void bilerp_kernel(const float* __restrict__ X,
                   const float* __restrict__ theta,
                   float* __restrict__ out) {
    const int ix = threadIdx.x;          // 0..255 == W_OUT lane (coalesced stores)
    const int iy = blockIdx.x & (H_OUT - 1);
    const int b  = blockIdx.x >> 8;      // H_OUT == 256

    const float* th = theta + b * 6;
    const float t00 = __ldg(th + 0), t01 = __ldg(th + 1), t02 = __ldg(th + 2);
    const float t10 = __ldg(th + 3), t11 = __ldg(th + 4), t12 = __ldg(th + 5);

    const float xc = fmaf((float)ix, 2.0f / (float)(W_OUT - 1), -1.0f);
    const float yc = fmaf((float)iy, 2.0f / (float)(H_OUT - 1), -1.0f);

    const float xs = t00 * xc + t01 * yc + t02;
    const float ys = t10 * xc + t11 * yc + t12;

    const float x = (xs + 1.0f) * ((float)W * 0.5f);
    const float y = (ys + 1.0f) * ((float)H * 0.5f);

    int x0 = (int)floorf(x);
    int x1 = x0 + 1;
    int y0 = (int)floorf(y);
    int y1 = y0 + 1;
    x0 = min(max(x0, 0), W - 1);
    x1 = min(max(x1, 0), W - 1);
    y0 = min(max(y0, 0), H - 1);
    y1 = min(max(y1, 0), H - 1);

    const float x0f = (float)x0, x1f = (float)x1;
    const float y0f = (float)y0, y1f = (float)y1;

    const float wa = (x1f - x) * (y1f - y);
    const float wb = (x1f - x) * (y - y0f);
    const float wc = (x - x0f) * (y1f - y);
    const float wd = (x - x0f) * (y - y0f);

    // Corner offsets (channel-invariant)
    const int oa = y0 * W + x0;
    const int ob = y1 * W + x0;
    const int oc = y0 * W + x1;
    const int od = y1 * W + x1;

    const float* __restrict__ xp = X + (size_t)b * C * HW;
    float* __restrict__ op = out + (size_t)b * C * HWO + (size_t)iy * W_OUT + ix;

    #pragma unroll 8
    for (int c = 0; c < C; ++c) {
        const float* p = xp + (size_t)c * HW;
        const float pa = __ldg(p + oa);
        const float pb = __ldg(p + ob);
        const float pc = __ldg(p + oc);
        const float pd = __ldg(p + od);
        op[(size_t)c * HWO] = wa * pa + wb * pb + wc * pc + wd * pd;
    }
}

extern "C" void kernel_launch(void* const* d_in, const int* in_sizes, int n_in,
                              void* d_out, int out_size) {
    const float* X     = (const float*)d_in[0];
    const float* theta = (const float*)d_in[1];
    // Defensive: if input order is swapped (theta is 96 elements), fix it.
    if (n_in >= 2 && in_sizes[0] == B * 6) {
        theta = (const float*)d_in[0];
        X     = (const float*)d_in[1];
    }
    float* out = (float*)d_out;

    dim3 grid(B * H_OUT);   // 4096 blocks: (b, iy)
    dim3 block(W_OUT);      // 256 threads: ix
    bilerp_kernel<<<grid, block>>>(X, theta, out);
}

// round 3
// speedup vs baseline: 1.9414x; 1.9414x over previous
#include <cuda_runtime.h>
#include <cuda_bf16.h>

// BilinearInterpolation (spatial transformer grid sample)
// X: [B, C, H, W] fp32, theta: [B, 6] fp32 -> out: [B, C, H_OUT, W_OUT] fp32
//
// R3 change vs R2: thread->pixel remap only. Each warp now covers an 8x4
// (ix x iy) patch instead of a 32x1 strip, shrinking the per-warp gather
// footprint (fewer distinct 128B input lines per warp LDG -> fewer L1tex
// wavefront replays). ALL arithmetic is kept expression-identical to the
// passing R2 kernel (rel_err 9.13e-4 is close to the 1e-3 bound; do not
// perturb rounding).

namespace {
constexpr int B = 16, C = 64, H = 256, W = 256;
constexpr int H_OUT = 256, W_OUT = 256;
constexpr int HW = H * W;           // channel stride in X
constexpr int HWO = H_OUT * W_OUT;  // channel stride in out
// Block tile: 32 (ix) x 8 (iy); warp tile: 8 (ix) x 4 (iy)
constexpr int TX = 32, TY = 8;
constexpr int NBX = W_OUT / TX;     // 8
constexpr int NBY = H_OUT / TY;     // 32
}

__global__ __launch_bounds__(256, 8)
void bilerp_kernel(const float* __restrict__ X,
                   const float* __restrict__ theta,
                   float* __restrict__ out) {
    // Block decode: blockIdx.x = b*NBY*NBX + by*NBX + bx
    const int bx = blockIdx.x & (NBX - 1);          // W tile
    const int by = (blockIdx.x >> 3) & (NBY - 1);   // H tile (NBX==8)
    const int b  = blockIdx.x >> 8;                 // NBX*NBY==256

    // Warp/lane decode: warp covers 8x4 patch
    const int lane = threadIdx.x & 31;
    const int w    = threadIdx.x >> 5;      // 0..7
    const int lx   = lane & 7;              // 0..7
    const int ly   = lane >> 3;             // 0..3
    const int wx   = w & 3;                 // 0..3  (4 warps across ix)
    const int wy   = w >> 2;                // 0..1  (2 warps across iy)

    const int ix = bx * TX + wx * 8 + lx;
    const int iy = by * TY + wy * 4 + ly;

    const float* th = theta + b * 6;
    const float t00 = __ldg(th + 0), t01 = __ldg(th + 1), t02 = __ldg(th + 2);
    const float t10 = __ldg(th + 3), t11 = __ldg(th + 4), t12 = __ldg(th + 5);

    const float xc = fmaf((float)ix, 2.0f / (float)(W_OUT - 1), -1.0f);
    const float yc = fmaf((float)iy, 2.0f / (float)(H_OUT - 1), -1.0f);

    const float xs = t00 * xc + t01 * yc + t02;
    const float ys = t10 * xc + t11 * yc + t12;

    const float x = (xs + 1.0f) * ((float)W * 0.5f);
    const float y = (ys + 1.0f) * ((float)H * 0.5f);

    int x0 = (int)floorf(x);
    int x1 = x0 + 1;
    int y0 = (int)floorf(y);
    int y1 = y0 + 1;
    x0 = min(max(x0, 0), W - 1);
    x1 = min(max(x1, 0), W - 1);
    y0 = min(max(y0, 0), H - 1);
    y1 = min(max(y1, 0), H - 1);

    const float x0f = (float)x0, x1f = (float)x1;
    const float y0f = (float)y0, y1f = (float)y1;

    const float wa = (x1f - x) * (y1f - y);
    const float wb = (x1f - x) * (y - y0f);
    const float wc = (x - x0f) * (y1f - y);
    const float wd = (x - x0f) * (y - y0f);

    // Corner offsets (channel-invariant)
    const int oa = y0 * W + x0;
    const int ob = y1 * W + x0;
    const int oc = y0 * W + x1;
    const int od = y1 * W + x1;

    const float* __restrict__ xp = X + (size_t)b * C * HW;
    float* __restrict__ op = out + (size_t)b * C * HWO + (size_t)iy * W_OUT + ix;

    #pragma unroll 8
    for (int c = 0; c < C; ++c) {
        const float* p = xp + (size_t)c * HW;
        const float pa = __ldg(p + oa);
        const float pb = __ldg(p + ob);
        const float pc = __ldg(p + oc);
        const float pd = __ldg(p + od);
        op[(size_t)c * HWO] = wa * pa + wb * pb + wc * pc + wd * pd;
    }
}

extern "C" void kernel_launch(void* const* d_in, const int* in_sizes, int n_in,
                              void* d_out, int out_size) {
    const float* X     = (const float*)d_in[0];
    const float* theta = (const float*)d_in[1];
    if (n_in >= 2 && in_sizes[0] == B * 6) {
        theta = (const float*)d_in[0];
        X     = (const float*)d_in[1];
    }
    float* out = (float*)d_out;

    dim3 grid(B * NBY * NBX);   // 4096 blocks
    dim3 block(256);
    bilerp_kernel<<<grid, block>>>(X, theta, out);
}

// round 4
// speedup vs baseline: 2.3739x; 1.2227x over previous
#include <cuda_runtime.h>
#include <cuda_bf16.h>

// BilinearInterpolation (spatial transformer grid sample)
// X: [B, C, H, W] fp32, theta: [B, 6] fp32 -> out: [B, C, H_OUT, W_OUT] fp32
//
// R4 change vs R3: warp-uniform clamp-path specialization. When x0==x1
// (x clamped), corner addresses satisfy oc==oa, od==ob, so reusing the
// loaded registers is BIT-IDENTICAL to issuing the duplicate LDGs (the
// weight chain is computed identically in every path). Warps fully inside
// a clamped region (checked with __all_sync, warp-uniform branch) skip
// 2-3 of the 4 gather LDGs, cutting L1tex wavefront work. Mixed warps use
// the unchanged 4-load path. rel_err must stay exactly 9.128e-4.

namespace {
constexpr int B = 16, C = 64, H = 256, W = 256;
constexpr int H_OUT = 256, W_OUT = 256;
constexpr int HW = H * W;           // channel stride in X
constexpr int HWO = H_OUT * W_OUT;  // channel stride in out
// Block tile: 32 (ix) x 8 (iy); warp tile: 8 (ix) x 4 (iy)
constexpr int NBX = W_OUT / 32;     // 8
constexpr int NBY = H_OUT / 8;      // 32
}

__global__ __launch_bounds__(256, 8)
void bilerp_kernel(const float* __restrict__ X,
                   const float* __restrict__ theta,
                   float* __restrict__ out) {
    const int bx = blockIdx.x & (NBX - 1);          // W tile
    const int by = (blockIdx.x >> 3) & (NBY - 1);   // H tile (NBX==8)
    const int b  = blockIdx.x >> 8;                 // NBX*NBY==256

    const int lane = threadIdx.x & 31;
    const int w    = threadIdx.x >> 5;      // 0..7
    const int lx   = lane & 7;              // 0..7
    const int ly   = lane >> 3;             // 0..3
    const int wx   = w & 3;                 // 0..3
    const int wy   = w >> 2;                // 0..1

    const int ix = bx * 32 + wx * 8 + lx;
    const int iy = by * 8 + wy * 4 + ly;

    const float* th = theta + b * 6;
    const float t00 = __ldg(th + 0), t01 = __ldg(th + 1), t02 = __ldg(th + 2);
    const float t10 = __ldg(th + 3), t11 = __ldg(th + 4), t12 = __ldg(th + 5);

    const float xc = fmaf((float)ix, 2.0f / (float)(W_OUT - 1), -1.0f);
    const float yc = fmaf((float)iy, 2.0f / (float)(H_OUT - 1), -1.0f);

    const float xs = t00 * xc + t01 * yc + t02;
    const float ys = t10 * xc + t11 * yc + t12;

    const float x = (xs + 1.0f) * ((float)W * 0.5f);
    const float y = (ys + 1.0f) * ((float)H * 0.5f);

    int x0 = (int)floorf(x);
    int x1 = x0 + 1;
    int y0 = (int)floorf(y);
    int y1 = y0 + 1;
    x0 = min(max(x0, 0), W - 1);
    x1 = min(max(x1, 0), W - 1);
    y0 = min(max(y0, 0), H - 1);
    y1 = min(max(y1, 0), H - 1);

    const float x0f = (float)x0, x1f = (float)x1;
    const float y0f = (float)y0, y1f = (float)y1;

    const float wa = (x1f - x) * (y1f - y);
    const float wb = (x1f - x) * (y - y0f);
    const float wc = (x - x0f) * (y1f - y);
    const float wd = (x - x0f) * (y - y0f);

    const int oa = y0 * W + x0;   // == oc when x0==x1 ; == ob when y0==y1
    const int ob = y1 * W + x0;
    const int oc = y0 * W + x1;
    const int od = y1 * W + x1;

    const float* __restrict__ xp = X + (size_t)b * C * HW;
    float* __restrict__ op = out + (size_t)b * C * HWO + (size_t)iy * W_OUT + ix;

    const bool xcl = (x0 == x1);
    const bool ycl = (y0 == y1);
    const unsigned full = 0xFFFFFFFFu;
    const bool allx = __all_sync(full, xcl);
    const bool ally = __all_sync(full, ycl);

    if (allx & ally) {
        // oa==ob==oc==od: one load feeds all four corners (bit-identical)
        #pragma unroll 8
        for (int c = 0; c < C; ++c) {
            const float* p = xp + (size_t)c * HW;
            const float pa = __ldg(p + oa);
            const float pb = pa, pc = pa, pd = pa;
            op[(size_t)c * HWO] = wa * pa + wb * pb + wc * pc + wd * pd;
        }
    } else if (allx) {
        // oc==oa, od==ob
        #pragma unroll 8
        for (int c = 0; c < C; ++c) {
            const float* p = xp + (size_t)c * HW;
            const float pa = __ldg(p + oa);
            const float pb = __ldg(p + ob);
            const float pc = pa, pd = pb;
            op[(size_t)c * HWO] = wa * pa + wb * pb + wc * pc + wd * pd;
        }
    } else if (ally) {
        // ob==oa, od==oc
        #pragma unroll 8
        for (int c = 0; c < C; ++c) {
            const float* p = xp + (size_t)c * HW;
            const float pa = __ldg(p + oa);
            const float pc = __ldg(p + oc);
            const float pb = pa, pd = pc;
            op[(size_t)c * HWO] = wa * pa + wb * pb + wc * pc + wd * pd;
        }
    } else {
        #pragma unroll 8
        for (int c = 0; c < C; ++c) {
            const float* p = xp + (size_t)c * HW;
            const float pa = __ldg(p + oa);
            const float pb = __ldg(p + ob);
            const float pc = __ldg(p + oc);
            const float pd = __ldg(p + od);
            op[(size_t)c * HWO] = wa * pa + wb * pb + wc * pc + wd * pd;
        }
    }
}

extern "C" void kernel_launch(void* const* d_in, const int* in_sizes, int n_in,
                              void* d_out, int out_size) {
    const float* X     = (const float*)d_in[0];
    const float* theta = (const float*)d_in[1];
    if (n_in >= 2 && in_sizes[0] == B * 6) {
        theta = (const float*)d_in[0];
        X     = (const float*)d_in[1];
    }
    float* out = (float*)d_out;

    dim3 grid(B * NBY * NBX);   // 4096 blocks
    dim3 block(256);
    bilerp_kernel<<<grid, block>>>(X, theta, out);
}